// round 12
// baseline (speedup 1.0000x reference)
#include <cuda_runtime.h>
#include <cuda_bf16.h>
#include <cstdint>
#include <math.h>

#define Bsz 16
#define Qs  64
#define Ns  16384
#define Ds  128

// ============================================================================
// helpers
// ============================================================================
__device__ __forceinline__ uint32_t smem_u32(const void* p) {
    uint32_t a;
    asm("{ .reg .u64 t; cvta.to.shared.u64 t, %1; cvt.u32.u64 %0, t; }"
        : "=r"(a) : "l"(p));
    return a;
}

__device__ __forceinline__ void ldm4(uint32_t& r0, uint32_t& r1, uint32_t& r2,
                                     uint32_t& r3, uint32_t addr) {
    asm volatile("ldmatrix.sync.aligned.m8n8.x4.shared.b16 {%0,%1,%2,%3}, [%4];"
                 : "=r"(r0), "=r"(r1), "=r"(r2), "=r"(r3) : "r"(addr));
}
__device__ __forceinline__ void ldm4t(uint32_t& r0, uint32_t& r1, uint32_t& r2,
                                      uint32_t& r3, uint32_t addr) {
    asm volatile("ldmatrix.sync.aligned.m8n8.x4.trans.shared.b16 {%0,%1,%2,%3}, [%4];"
                 : "=r"(r0), "=r"(r1), "=r"(r2), "=r"(r3) : "r"(addr));
}
__device__ __forceinline__ void mma_bf16(float* c, const uint32_t* a,
                                         uint32_t b0, uint32_t b1) {
    asm volatile(
        "mma.sync.aligned.m16n8k16.row.col.f32.bf16.bf16.f32 "
        "{%0,%1,%2,%3}, {%4,%5,%6,%7}, {%8,%9}, {%0,%1,%2,%3};"
        : "+f"(c[0]), "+f"(c[1]), "+f"(c[2]), "+f"(c[3])
        : "r"(a[0]), "r"(a[1]), "r"(a[2]), "r"(a[3]), "r"(b0), "r"(b1));
}

// split fp32 float4 -> bf16 hi (8B) + bf16 lo (8B)
__device__ __forceinline__ void cvt_split(char* hi, char* lo, float4 v) {
    __nv_bfloat16 h0 = __float2bfloat16(v.x);
    __nv_bfloat16 h1 = __float2bfloat16(v.y);
    __nv_bfloat16 h2 = __float2bfloat16(v.z);
    __nv_bfloat16 h3 = __float2bfloat16(v.w);
    __nv_bfloat16 g0 = __float2bfloat16(v.x - __bfloat162float(h0));
    __nv_bfloat16 g1 = __float2bfloat16(v.y - __bfloat162float(h1));
    __nv_bfloat16 g2 = __float2bfloat16(v.z - __bfloat162float(h2));
    __nv_bfloat16 g3 = __float2bfloat16(v.w - __bfloat162float(h3));
    uint2 hp, lp;
    hp.x = (uint32_t)__bfloat16_as_ushort(h0) | ((uint32_t)__bfloat16_as_ushort(h1) << 16);
    hp.y = (uint32_t)__bfloat16_as_ushort(h2) | ((uint32_t)__bfloat16_as_ushort(h3) << 16);
    lp.x = (uint32_t)__bfloat16_as_ushort(g0) | ((uint32_t)__bfloat16_as_ushort(g1) << 16);
    lp.y = (uint32_t)__bfloat16_as_ushort(g2) | ((uint32_t)__bfloat16_as_ushort(g3) << 16);
    *(uint2*)hi = hp;
    *(uint2*)lo = lp;
}

// ============================================================================
// Kernel 1: logits GEMM — R4-exact structure (best measured: 66.7us)
// ============================================================================
static constexpr int L_AHI = 0;
static constexpr int L_ALO = 34816;             // 128*136*2
static constexpr int L_QHI = 69632;
static constexpr int L_QLO = 87040;             // + 64*136*2
static constexpr int L_TOTAL = 104448;

__global__ void __launch_bounds__(256, 2)
k_logits_mma(const float* __restrict__ qv, const float* __restrict__ A,
             float* __restrict__ logits) {
    extern __shared__ char sm[];
    const int tid = threadIdx.x;
    const int b = blockIdx.y, n0 = blockIdx.x * 128;

    // ---- load + split A tile [128n x 128d], MLP-8 prefetch ----
    const float* ab = A + ((size_t)b * Ns + n0) * Ds;
    #pragma unroll
    for (int g = 0; g < 2; g++) {
        float4 va[8];
        #pragma unroll
        for (int i = 0; i < 8; i++) {
            int f = tid + (g * 8 + i) * 256;
            va[i] = *(const float4*)(ab + (size_t)(f >> 5) * Ds + (f & 31) * 4);
        }
        #pragma unroll
        for (int i = 0; i < 8; i++) {
            int f = tid + (g * 8 + i) * 256;
            int off = ((f >> 5) * 136 + (f & 31) * 4) * 2;
            cvt_split(sm + L_AHI + off, sm + L_ALO + off, va[i]);
        }
    }
    // ---- load + split Q tile [64q x 128d], MLP-8 ----
    const float* qb = qv + (size_t)b * Qs * Ds;
    {
        float4 vq[8];
        #pragma unroll
        for (int i = 0; i < 8; i++) {
            int f = tid + i * 256;
            vq[i] = *(const float4*)(qb + (size_t)(f >> 5) * Ds + (f & 31) * 4);
        }
        #pragma unroll
        for (int i = 0; i < 8; i++) {
            int f = tid + i * 256;
            int off = ((f >> 5) * 136 + (f & 31) * 4) * 2;
            cvt_split(sm + L_QHI + off, sm + L_QLO + off, vq[i]);
        }
    }
    __syncthreads();

    const int wid = tid >> 5, lane = tid & 31;
    const int wm = wid & 3;        // n dim: 4 warps x 32
    const int wq = wid >> 2;       // q dim: 2 warps x 32

    float acc[2][4][4];
    #pragma unroll
    for (int mi = 0; mi < 2; mi++)
        #pragma unroll
        for (int ni = 0; ni < 4; ni++)
            #pragma unroll
            for (int r = 0; r < 4; r++) acc[mi][ni][r] = 0.f;

    const uint32_t sb = smem_u32(sm);
    const int aoff[3] = { L_AHI, L_AHI, L_ALO };
    const int qoff[3] = { L_QHI, L_QLO, L_QHI };

    const uint32_t a_row = (uint32_t)(wm * 32 + (lane & 15));
    const uint32_t a_kb  = (uint32_t)(((lane >> 4) << 3) * 2);
    const uint32_t q_row0 = (uint32_t)(wq * 32 + ((lane >> 4) << 3) + (lane & 7));
    const uint32_t q_kb  = (uint32_t)((((lane >> 3) & 1) << 3) * 2);

    #pragma unroll
    for (int p = 0; p < 3; p++) {
        const uint32_t abase = sb + aoff[p] + a_row * 272 + a_kb;
        const uint32_t qbase = sb + qoff[p] + q_row0 * 272 + q_kb;
        #pragma unroll
        for (int k = 0; k < 8; k++) {
            uint32_t af[2][4];
            ldm4(af[0][0], af[0][1], af[0][2], af[0][3], abase + k * 32);
            ldm4(af[1][0], af[1][1], af[1][2], af[1][3], abase + 16 * 272 + k * 32);
            uint32_t bf[4][2];
            {
                uint32_t r0, r1, r2, r3;
                ldm4(r0, r1, r2, r3, qbase + k * 32);
                bf[0][0] = r0; bf[0][1] = r1; bf[1][0] = r2; bf[1][1] = r3;
                ldm4(r0, r1, r2, r3, qbase + 16 * 272 + k * 32);
                bf[2][0] = r0; bf[2][1] = r1; bf[3][0] = r2; bf[3][1] = r3;
            }
            #pragma unroll
            for (int mi = 0; mi < 2; mi++)
                #pragma unroll
                for (int ni = 0; ni < 4; ni++)
                    mma_bf16(acc[mi][ni], af[mi], bf[ni][0], bf[ni][1]);
        }
    }
    __syncthreads();

    // ---- stage D to smem [q][n], stride 132 fp32, then coalesced store ----
    float* sD = (float*)sm;
    const int group = lane >> 2, tc = lane & 3;
    #pragma unroll
    for (int mi = 0; mi < 2; mi++)
        #pragma unroll
        for (int ni = 0; ni < 4; ni++)
            #pragma unroll
            for (int r = 0; r < 4; r++) {
                int nl = wm * 32 + mi * 16 + group + ((r >> 1) << 3);
                int ql = wq * 32 + ni * 8 + (tc << 1) + (r & 1);
                sD[ql * 132 + nl] = acc[mi][ni][r];
            }
    __syncthreads();

    float* lb = logits + (size_t)b * Qs * Ns + n0;
    #pragma unroll
    for (int i = 0; i < 8; i++) {
        int f = tid + i * 256;
        int q = f >> 5, c4 = f & 31;
        float4 v = *(const float4*)&sD[q * 132 + c4 * 4];
        *(float4*)(lb + (size_t)q * Ns + c4 * 4) = v;
    }
}

// ============================================================================
// Kernel 2: masked max-free softmax over N per (b,q) row.
// ============================================================================
__global__ void k_softmax(const float* __restrict__ logits,
                          const int* __restrict__ node_nums,
                          float* __restrict__ prob) {
    const int bq  = blockIdx.x;
    const int b   = bq >> 6;
    const int nn  = node_nums[b];
    const int tid = threadIdx.x;

    const float* row = logits + (size_t)bq * Ns;
    float v[64];
    #pragma unroll
    for (int i = 0; i < 64; i++) v[i] = row[tid + i * 256];

    float s = 0.f;
    #pragma unroll
    for (int i = 0; i < 64; i++) {
        int n = tid + i * 256;
        float e = (n < nn) ? __expf(v[i]) : 0.f;
        v[i] = e;
        s += e;
    }
    __shared__ float reds[8];
    #pragma unroll
    for (int o = 16; o > 0; o >>= 1)
        s += __shfl_xor_sync(0xffffffffu, s, o);
    if ((tid & 31) == 0) reds[tid >> 5] = s;
    __syncthreads();
    {
        float t = 0.f;
        #pragma unroll
        for (int w = 0; w < 8; w++) t += reds[w];
        s = t;
    }

    const float inv = 1.f / s;
    float* prow = prob + (size_t)bq * Ns;
    #pragma unroll
    for (int i = 0; i < 64; i++) prow[tid + i * 256] = v[i] * inv;
}

// ============================================================================
// Kernel 3: res GEMM — R4-exact structure, but 3 CTAs/SM
// (smem 53KB x 3 = 160KB fits; reg cap 84 — same acc/fragment footprint
//  that compiled to 80 regs in the R9 k_logits variant).
// ============================================================================
static constexpr int R_PHI = 0;
static constexpr int R_PLO = 9216;              // 64*72*2
static constexpr int R_AHI = 18432;
static constexpr int R_ALO = 35840;             // + 64*136*2
static constexpr int R_TOTAL = 53248;

__global__ void __launch_bounds__(256, 3)
k_res_mma(const float* __restrict__ P, const float* __restrict__ A,
          float* __restrict__ res) {
    extern __shared__ char sm[];
    const int b = blockIdx.x;
    const int kbase = blockIdx.y * 512;
    const int tid = threadIdx.x;
    const int wid = tid >> 5, lane = tid & 31;
    const int wm = wid & 1;        // q dim: 2 warps x 32
    const int wd = wid >> 1;       // d dim: 4 warps x 32

    float acc[2][4][4];
    #pragma unroll
    for (int mi = 0; mi < 2; mi++)
        #pragma unroll
        for (int ni = 0; ni < 4; ni++)
            #pragma unroll
            for (int r = 0; r < 4; r++) acc[mi][ni][r] = 0.f;

    const float* pbase = P + (size_t)b * Qs * Ns;
    const float* abase = A + (size_t)b * Ns * Ds;
    const uint32_t sb = smem_u32(sm);

    const int poff[3] = { R_PHI, R_PHI, R_PLO };
    const int aoff[3] = { R_AHI, R_ALO, R_AHI };

    const uint32_t p_row = (uint32_t)(wm * 32 + (lane & 15));
    const uint32_t p_kb  = (uint32_t)(((lane >> 4) << 3) * 2);
    const uint32_t a_krow0 = (uint32_t)((((lane >> 3) & 1) << 3) + (lane & 7));
    const uint32_t a_dcol  = (uint32_t)((wd * 32 + ((lane >> 4) << 3)) * 2);

    for (int kt = 0; kt < 8; kt++) {
        const int kk = kbase + kt * 64;
        {
            float4 vp[4], va[4];
            #pragma unroll
            for (int i = 0; i < 4; i++) {
                int f = tid + i * 256;
                vp[i] = *(const float4*)(pbase + (size_t)(f >> 4) * Ns + kk + (f & 15) * 4);
            }
            #pragma unroll
            for (int i = 0; i < 4; i++) {
                int f = tid + i * 256;
                va[i] = *(const float4*)(abase + (size_t)(kk + (f >> 5)) * Ds + (f & 31) * 4);
            }
            #pragma unroll
            for (int i = 0; i < 4; i++) {
                int f = tid + i * 256;
                int off = ((f >> 4) * 72 + (f & 15) * 4) * 2;
                cvt_split(sm + R_PHI + off, sm + R_PLO + off, vp[i]);
            }
            #pragma unroll
            for (int i = 0; i < 4; i++) {
                int f = tid + i * 256;
                int off = ((f >> 5) * 136 + (f & 31) * 4) * 2;
                cvt_split(sm + R_AHI + off, sm + R_ALO + off, va[i]);
            }
        }
        {
            float4 va[4];
            #pragma unroll
            for (int i = 0; i < 4; i++) {
                int f = tid + (4 + i) * 256;
                va[i] = *(const float4*)(abase + (size_t)(kk + (f >> 5)) * Ds + (f & 31) * 4);
            }
            #pragma unroll
            for (int i = 0; i < 4; i++) {
                int f = tid + (4 + i) * 256;
                int off = ((f >> 5) * 136 + (f & 31) * 4) * 2;
                cvt_split(sm + R_AHI + off, sm + R_ALO + off, va[i]);
            }
        }
        __syncthreads();

        #pragma unroll
        for (int p = 0; p < 3; p++) {
            const uint32_t pb_ = sb + poff[p] + p_row * 144 + p_kb;
            const uint32_t ab_ = sb + aoff[p] + a_krow0 * 272 + a_dcol;
            #pragma unroll
            for (int k = 0; k < 4; k++) {
                uint32_t af[2][4];
                ldm4(af[0][0], af[0][1], af[0][2], af[0][3], pb_ + k * 32);
                ldm4(af[1][0], af[1][1], af[1][2], af[1][3], pb_ + 16 * 144 + k * 32);
                uint32_t bfr[4][2];
                {
                    uint32_t r0, r1, r2, r3;
                    ldm4t(r0, r1, r2, r3, ab_ + k * 16 * 272);
                    bfr[0][0] = r0; bfr[0][1] = r1; bfr[1][0] = r2; bfr[1][1] = r3;
                    ldm4t(r0, r1, r2, r3, ab_ + k * 16 * 272 + 16 * 2);
                    bfr[2][0] = r0; bfr[2][1] = r1; bfr[3][0] = r2; bfr[3][1] = r3;
                }
                #pragma unroll
                for (int mi = 0; mi < 2; mi++)
                    #pragma unroll
                    for (int ni = 0; ni < 4; ni++)
                        mma_bf16(acc[mi][ni], af[mi], bfr[ni][0], bfr[ni][1]);
            }
        }
        __syncthreads();
    }

    // epilogue: atomic accumulate into res[b][q][d]
    const int group = lane >> 2, tc = lane & 3;
    float* rb = res + (size_t)b * Qs * Ds;
    #pragma unroll
    for (int mi = 0; mi < 2; mi++)
        #pragma unroll
        for (int ni = 0; ni < 4; ni++)
            #pragma unroll
            for (int r = 0; r < 4; r++) {
                int q = wm * 32 + mi * 16 + group + ((r >> 1) << 3);
                int d = wd * 32 + ni * 8 + (tc << 1) + (r & 1);
                atomicAdd(rb + (size_t)q * Ds + d, acc[mi][ni][r]);
            }
}

// ---------------------------------------------------------------------------
extern "C" void kernel_launch(void* const* d_in, const int* in_sizes, int n_in,
                              void* d_out, int out_size) {
    const float* qv = (const float*)d_in[0];
    const float* A  = (const float*)d_in[1];
    const int*   nn = (const int*)d_in[2];

    float* out_res  = (float*)d_out;                        // [B,Q,D]
    float* out_soft = out_res  + (size_t)Bsz * Qs * Ds;     // [B,Q,N]
    float* out_log  = out_soft + (size_t)Bsz * Qs * Ns;     // [B,Q,N]

    cudaMemsetAsync(out_res, 0, (size_t)Bsz * Qs * Ds * sizeof(float));

    cudaFuncSetAttribute(k_logits_mma,
                         cudaFuncAttributeMaxDynamicSharedMemorySize, L_TOTAL);
    cudaFuncSetAttribute(k_res_mma,
                         cudaFuncAttributeMaxDynamicSharedMemorySize, R_TOTAL);

    k_logits_mma<<<dim3(Ns / 128, Bsz), 256, L_TOTAL>>>(qv, A, out_log);
    k_softmax<<<Bsz * Qs, 256>>>(out_log, nn, out_soft);
    k_res_mma<<<dim3(Bsz, 32), 256, R_TOTAL>>>(out_soft, A, out_res);
}

// round 13
// speedup vs baseline: 1.1738x; 1.1738x over previous
#include <cuda_runtime.h>
#include <cuda_bf16.h>
#include <cstdint>
#include <math.h>

#define Bsz 16
#define Qs  64
#define Ns  16384
#define Ds  128

// ============================================================================
// helpers
// ============================================================================
__device__ __forceinline__ uint32_t smem_u32(const void* p) {
    uint32_t a;
    asm("{ .reg .u64 t; cvta.to.shared.u64 t, %1; cvt.u32.u64 %0, t; }"
        : "=r"(a) : "l"(p));
    return a;
}

__device__ __forceinline__ void ldm4(uint32_t& r0, uint32_t& r1, uint32_t& r2,
                                     uint32_t& r3, uint32_t addr) {
    asm volatile("ldmatrix.sync.aligned.m8n8.x4.shared.b16 {%0,%1,%2,%3}, [%4];"
                 : "=r"(r0), "=r"(r1), "=r"(r2), "=r"(r3) : "r"(addr));
}
__device__ __forceinline__ void ldm4t(uint32_t& r0, uint32_t& r1, uint32_t& r2,
                                      uint32_t& r3, uint32_t addr) {
    asm volatile("ldmatrix.sync.aligned.m8n8.x4.trans.shared.b16 {%0,%1,%2,%3}, [%4];"
                 : "=r"(r0), "=r"(r1), "=r"(r2), "=r"(r3) : "r"(addr));
}
__device__ __forceinline__ void mma_bf16(float* c, const uint32_t* a,
                                         uint32_t b0, uint32_t b1) {
    asm volatile(
        "mma.sync.aligned.m16n8k16.row.col.f32.bf16.bf16.f32 "
        "{%0,%1,%2,%3}, {%4,%5,%6,%7}, {%8,%9}, {%0,%1,%2,%3};"
        : "+f"(c[0]), "+f"(c[1]), "+f"(c[2]), "+f"(c[3])
        : "r"(a[0]), "r"(a[1]), "r"(a[2]), "r"(a[3]), "r"(b0), "r"(b1));
}
__device__ __forceinline__ void cp_async16(uint32_t smem_dst, const void* gsrc) {
    asm volatile("cp.async.cg.shared.global [%0], [%1], 16;"
                 :: "r"(smem_dst), "l"(gsrc) : "memory");
}
#define CP_COMMIT() asm volatile("cp.async.commit_group;" ::: "memory")
#define CP_WAIT0()  asm volatile("cp.async.wait_group 0;" ::: "memory")

// split fp32 float4 -> bf16 hi (8B) + bf16 lo (8B)
__device__ __forceinline__ void cvt_split(char* hi, char* lo, float4 v) {
    __nv_bfloat16 h0 = __float2bfloat16(v.x);
    __nv_bfloat16 h1 = __float2bfloat16(v.y);
    __nv_bfloat16 h2 = __float2bfloat16(v.z);
    __nv_bfloat16 h3 = __float2bfloat16(v.w);
    __nv_bfloat16 g0 = __float2bfloat16(v.x - __bfloat162float(h0));
    __nv_bfloat16 g1 = __float2bfloat16(v.y - __bfloat162float(h1));
    __nv_bfloat16 g2 = __float2bfloat16(v.z - __bfloat162float(h2));
    __nv_bfloat16 g3 = __float2bfloat16(v.w - __bfloat162float(h3));
    uint2 hp, lp;
    hp.x = (uint32_t)__bfloat16_as_ushort(h0) | ((uint32_t)__bfloat16_as_ushort(h1) << 16);
    hp.y = (uint32_t)__bfloat16_as_ushort(h2) | ((uint32_t)__bfloat16_as_ushort(h3) << 16);
    lp.x = (uint32_t)__bfloat16_as_ushort(g0) | ((uint32_t)__bfloat16_as_ushort(g1) << 16);
    lp.y = (uint32_t)__bfloat16_as_ushort(g2) | ((uint32_t)__bfloat16_as_ushort(g3) << 16);
    *(uint2*)hi = hp;
    *(uint2*)lo = lp;
}

// ============================================================================
// Kernel 1: logits GEMM — R4-exact structure (best measured: 66.7us)
// ============================================================================
static constexpr int L_AHI = 0;
static constexpr int L_ALO = 34816;             // 128*136*2
static constexpr int L_QHI = 69632;
static constexpr int L_QLO = 87040;             // + 64*136*2
static constexpr int L_TOTAL = 104448;

__global__ void __launch_bounds__(256, 2)
k_logits_mma(const float* __restrict__ qv, const float* __restrict__ A,
             float* __restrict__ logits) {
    extern __shared__ char sm[];
    const int tid = threadIdx.x;
    const int b = blockIdx.y, n0 = blockIdx.x * 128;

    // ---- load + split A tile [128n x 128d], MLP-8 prefetch ----
    const float* ab = A + ((size_t)b * Ns + n0) * Ds;
    #pragma unroll
    for (int g = 0; g < 2; g++) {
        float4 va[8];
        #pragma unroll
        for (int i = 0; i < 8; i++) {
            int f = tid + (g * 8 + i) * 256;
            va[i] = *(const float4*)(ab + (size_t)(f >> 5) * Ds + (f & 31) * 4);
        }
        #pragma unroll
        for (int i = 0; i < 8; i++) {
            int f = tid + (g * 8 + i) * 256;
            int off = ((f >> 5) * 136 + (f & 31) * 4) * 2;
            cvt_split(sm + L_AHI + off, sm + L_ALO + off, va[i]);
        }
    }
    // ---- load + split Q tile [64q x 128d], MLP-8 ----
    const float* qb = qv + (size_t)b * Qs * Ds;
    {
        float4 vq[8];
        #pragma unroll
        for (int i = 0; i < 8; i++) {
            int f = tid + i * 256;
            vq[i] = *(const float4*)(qb + (size_t)(f >> 5) * Ds + (f & 31) * 4);
        }
        #pragma unroll
        for (int i = 0; i < 8; i++) {
            int f = tid + i * 256;
            int off = ((f >> 5) * 136 + (f & 31) * 4) * 2;
            cvt_split(sm + L_QHI + off, sm + L_QLO + off, vq[i]);
        }
    }
    __syncthreads();

    const int wid = tid >> 5, lane = tid & 31;
    const int wm = wid & 3;        // n dim: 4 warps x 32
    const int wq = wid >> 2;       // q dim: 2 warps x 32

    float acc[2][4][4];
    #pragma unroll
    for (int mi = 0; mi < 2; mi++)
        #pragma unroll
        for (int ni = 0; ni < 4; ni++)
            #pragma unroll
            for (int r = 0; r < 4; r++) acc[mi][ni][r] = 0.f;

    const uint32_t sb = smem_u32(sm);
    const int aoff[3] = { L_AHI, L_AHI, L_ALO };
    const int qoff[3] = { L_QHI, L_QLO, L_QHI };

    const uint32_t a_row = (uint32_t)(wm * 32 + (lane & 15));
    const uint32_t a_kb  = (uint32_t)(((lane >> 4) << 3) * 2);
    const uint32_t q_row0 = (uint32_t)(wq * 32 + ((lane >> 4) << 3) + (lane & 7));
    const uint32_t q_kb  = (uint32_t)((((lane >> 3) & 1) << 3) * 2);

    #pragma unroll
    for (int p = 0; p < 3; p++) {
        const uint32_t abase = sb + aoff[p] + a_row * 272 + a_kb;
        const uint32_t qbase = sb + qoff[p] + q_row0 * 272 + q_kb;
        #pragma unroll
        for (int k = 0; k < 8; k++) {
            uint32_t af[2][4];
            ldm4(af[0][0], af[0][1], af[0][2], af[0][3], abase + k * 32);
            ldm4(af[1][0], af[1][1], af[1][2], af[1][3], abase + 16 * 272 + k * 32);
            uint32_t bf[4][2];
            {
                uint32_t r0, r1, r2, r3;
                ldm4(r0, r1, r2, r3, qbase + k * 32);
                bf[0][0] = r0; bf[0][1] = r1; bf[1][0] = r2; bf[1][1] = r3;
                ldm4(r0, r1, r2, r3, qbase + 16 * 272 + k * 32);
                bf[2][0] = r0; bf[2][1] = r1; bf[3][0] = r2; bf[3][1] = r3;
            }
            #pragma unroll
            for (int mi = 0; mi < 2; mi++)
                #pragma unroll
                for (int ni = 0; ni < 4; ni++)
                    mma_bf16(acc[mi][ni], af[mi], bf[ni][0], bf[ni][1]);
        }
    }
    __syncthreads();

    // ---- stage D to smem [q][n], stride 132 fp32, then coalesced store ----
    float* sD = (float*)sm;
    const int group = lane >> 2, tc = lane & 3;
    #pragma unroll
    for (int mi = 0; mi < 2; mi++)
        #pragma unroll
        for (int ni = 0; ni < 4; ni++)
            #pragma unroll
            for (int r = 0; r < 4; r++) {
                int nl = wm * 32 + mi * 16 + group + ((r >> 1) << 3);
                int ql = wq * 32 + ni * 8 + (tc << 1) + (r & 1);
                sD[ql * 132 + nl] = acc[mi][ni][r];
            }
    __syncthreads();

    float* lb = logits + (size_t)b * Qs * Ns + n0;
    #pragma unroll
    for (int i = 0; i < 8; i++) {
        int f = tid + i * 256;
        int q = f >> 5, c4 = f & 31;
        float4 v = *(const float4*)&sD[q * 132 + c4 * 4];
        *(float4*)(lb + (size_t)q * Ns + c4 * 4) = v;
    }
}

// ============================================================================
// Kernel 2: masked max-free softmax over N per (b,q) row.
// ============================================================================
__global__ void k_softmax(const float* __restrict__ logits,
                          const int* __restrict__ node_nums,
                          float* __restrict__ prob) {
    const int bq  = blockIdx.x;
    const int b   = bq >> 6;
    const int nn  = node_nums[b];
    const int tid = threadIdx.x;

    const float* row = logits + (size_t)bq * Ns;
    float v[64];
    #pragma unroll
    for (int i = 0; i < 64; i++) v[i] = row[tid + i * 256];

    float s = 0.f;
    #pragma unroll
    for (int i = 0; i < 64; i++) {
        int n = tid + i * 256;
        float e = (n < nn) ? __expf(v[i]) : 0.f;
        v[i] = e;
        s += e;
    }
    __shared__ float reds[8];
    #pragma unroll
    for (int o = 16; o > 0; o >>= 1)
        s += __shfl_xor_sync(0xffffffffu, s, o);
    if ((tid & 31) == 0) reds[tid >> 5] = s;
    __syncthreads();
    {
        float t = 0.f;
        #pragma unroll
        for (int w = 0; w < 8; w++) t += reds[w];
        s = t;
    }

    const float inv = 1.f / s;
    float* prow = prob + (size_t)bq * Ns;
    #pragma unroll
    for (int i = 0; i < 64; i++) prow[tid + i * 256] = v[i] * inv;
}

// ============================================================================
// Kernel 3: res GEMM — cp.async staging pipeline (zero register cost).
// smem: bf16 operand buffers (52KB) + fp32 staging P(16KB)+A(32KB) = 100KB.
// Loop: wait(k) -> sync -> cvt from staging -> sync -> cp.async(k+1) -> MMA.
// ============================================================================
static constexpr int R_PHI = 0;
static constexpr int R_PLO = 9216;              // 64*72*2
static constexpr int R_AHI = 18432;
static constexpr int R_ALO = 35840;             // + 64*136*2
static constexpr int R_SP  = 53248;             // fp32 P staging [64][64]
static constexpr int R_SA  = 69632;             // fp32 A staging [64][128]
static constexpr int R_TOTAL = 102400;

__global__ void __launch_bounds__(256, 2)
k_res_mma(const float* __restrict__ P, const float* __restrict__ A,
          float* __restrict__ res) {
    extern __shared__ char sm[];
    const int b = blockIdx.x;
    const int kbase = blockIdx.y * 512;
    const int tid = threadIdx.x;
    const int wid = tid >> 5, lane = tid & 31;
    const int wm = wid & 1;        // q dim: 2 warps x 32
    const int wd = wid >> 1;       // d dim: 4 warps x 32

    float acc[2][4][4];
    #pragma unroll
    for (int mi = 0; mi < 2; mi++)
        #pragma unroll
        for (int ni = 0; ni < 4; ni++)
            #pragma unroll
            for (int r = 0; r < 4; r++) acc[mi][ni][r] = 0.f;

    const float* pbase = P + (size_t)b * Qs * Ns;
    const float* abase = A + (size_t)b * Ns * Ds;
    const uint32_t sb = smem_u32(sm);

    const int poff[3] = { R_PHI, R_PHI, R_PLO };
    const int aoff[3] = { R_AHI, R_ALO, R_AHI };

    const uint32_t p_row = (uint32_t)(wm * 32 + (lane & 15));
    const uint32_t p_kb  = (uint32_t)(((lane >> 4) << 3) * 2);
    const uint32_t a_krow0 = (uint32_t)((((lane >> 3) & 1) << 3) + (lane & 7));
    const uint32_t a_dcol  = (uint32_t)((wd * 32 + ((lane >> 4) << 3)) * 2);

    // ---- prologue: cp.async stage 0 ----
    {
        const int kk = kbase;
        #pragma unroll
        for (int i = 0; i < 4; i++) {
            int f = tid + i * 256;
            cp_async16(sb + R_SP + f * 16,
                       pbase + (size_t)(f >> 4) * Ns + kk + (f & 15) * 4);
        }
        #pragma unroll
        for (int i = 0; i < 8; i++) {
            int f = tid + i * 256;
            cp_async16(sb + R_SA + f * 16,
                       abase + (size_t)(kk + (f >> 5)) * Ds + (f & 31) * 4);
        }
        CP_COMMIT();
    }

    for (int kt = 0; kt < 8; kt++) {
        CP_WAIT0();
        __syncthreads();   // staging visible to all; prev MMA done

        // ---- cvt staging -> bf16 operand buffers ----
        #pragma unroll
        for (int i = 0; i < 4; i++) {
            int f = tid + i * 256;
            float4 v = *(const float4*)(sm + R_SP + f * 16);
            int off = ((f >> 4) * 72 + (f & 15) * 4) * 2;
            cvt_split(sm + R_PHI + off, sm + R_PLO + off, v);
        }
        #pragma unroll
        for (int i = 0; i < 8; i++) {
            int f = tid + i * 256;
            float4 v = *(const float4*)(sm + R_SA + f * 16);
            int off = ((f >> 5) * 136 + (f & 31) * 4) * 2;
            cvt_split(sm + R_AHI + off, sm + R_ALO + off, v);
        }
        __syncthreads();   // bf16 ready; staging fully consumed

        // ---- cp.async next stage (overlaps MMA below) ----
        if (kt < 7) {
            const int kk2 = kbase + (kt + 1) * 64;
            #pragma unroll
            for (int i = 0; i < 4; i++) {
                int f = tid + i * 256;
                cp_async16(sb + R_SP + f * 16,
                           pbase + (size_t)(f >> 4) * Ns + kk2 + (f & 15) * 4);
            }
            #pragma unroll
            for (int i = 0; i < 8; i++) {
                int f = tid + i * 256;
                cp_async16(sb + R_SA + f * 16,
                           abase + (size_t)(kk2 + (f >> 5)) * Ds + (f & 31) * 4);
            }
            CP_COMMIT();
        }

        // ---- MMA phase (3-pass emulation) ----
        #pragma unroll
        for (int p = 0; p < 3; p++) {
            const uint32_t pb_ = sb + poff[p] + p_row * 144 + p_kb;
            const uint32_t ab_ = sb + aoff[p] + a_krow0 * 272 + a_dcol;
            #pragma unroll
            for (int k = 0; k < 4; k++) {
                uint32_t af[2][4];
                ldm4(af[0][0], af[0][1], af[0][2], af[0][3], pb_ + k * 32);
                ldm4(af[1][0], af[1][1], af[1][2], af[1][3], pb_ + 16 * 144 + k * 32);
                uint32_t bfr[4][2];
                {
                    uint32_t r0, r1, r2, r3;
                    ldm4t(r0, r1, r2, r3, ab_ + k * 16 * 272);
                    bfr[0][0] = r0; bfr[0][1] = r1; bfr[1][0] = r2; bfr[1][1] = r3;
                    ldm4t(r0, r1, r2, r3, ab_ + k * 16 * 272 + 16 * 2);
                    bfr[2][0] = r0; bfr[2][1] = r1; bfr[3][0] = r2; bfr[3][1] = r3;
                }
                #pragma unroll
                for (int mi = 0; mi < 2; mi++)
                    #pragma unroll
                    for (int ni = 0; ni < 4; ni++)
                        mma_bf16(acc[mi][ni], af[mi], bfr[ni][0], bfr[ni][1]);
            }
        }
    }

    // epilogue: atomic accumulate into res[b][q][d]
    const int group = lane >> 2, tc = lane & 3;
    float* rb = res + (size_t)b * Qs * Ds;
    #pragma unroll
    for (int mi = 0; mi < 2; mi++)
        #pragma unroll
        for (int ni = 0; ni < 4; ni++)
            #pragma unroll
            for (int r = 0; r < 4; r++) {
                int q = wm * 32 + mi * 16 + group + ((r >> 1) << 3);
                int d = wd * 32 + ni * 8 + (tc << 1) + (r & 1);
                atomicAdd(rb + (size_t)q * Ds + d, acc[mi][ni][r]);
            }
}

// ---------------------------------------------------------------------------
extern "C" void kernel_launch(void* const* d_in, const int* in_sizes, int n_in,
                              void* d_out, int out_size) {
    const float* qv = (const float*)d_in[0];
    const float* A  = (const float*)d_in[1];
    const int*   nn = (const int*)d_in[2];

    float* out_res  = (float*)d_out;                        // [B,Q,D]
    float* out_soft = out_res  + (size_t)Bsz * Qs * Ds;     // [B,Q,N]
    float* out_log  = out_soft + (size_t)Bsz * Qs * Ns;     // [B,Q,N]

    cudaMemsetAsync(out_res, 0, (size_t)Bsz * Qs * Ds * sizeof(float));

    cudaFuncSetAttribute(k_logits_mma,
                         cudaFuncAttributeMaxDynamicSharedMemorySize, L_TOTAL);
    cudaFuncSetAttribute(k_res_mma,
                         cudaFuncAttributeMaxDynamicSharedMemorySize, R_TOTAL);

    k_logits_mma<<<dim3(Ns / 128, Bsz), 256, L_TOTAL>>>(qv, A, out_log);
    k_softmax<<<Bsz * Qs, 256>>>(out_log, nn, out_soft);
    k_res_mma<<<dim3(Bsz, 32), 256, R_TOTAL>>>(out_soft, A, out_res);
}

// round 14
// speedup vs baseline: 1.2455x; 1.0611x over previous
#include <cuda_runtime.h>
#include <cuda_bf16.h>
#include <cstdint>
#include <math.h>

#define Bsz 16
#define Qs  64
#define Ns  16384
#define Ds  128
#define NCHUNK 4
#define CB (Bsz / NCHUNK)      // 4 batches per chunk

// ============================================================================
// helpers
// ============================================================================
__device__ __forceinline__ uint32_t smem_u32(const void* p) {
    uint32_t a;
    asm("{ .reg .u64 t; cvta.to.shared.u64 t, %1; cvt.u32.u64 %0, t; }"
        : "=r"(a) : "l"(p));
    return a;
}

__device__ __forceinline__ void ldm4(uint32_t& r0, uint32_t& r1, uint32_t& r2,
                                     uint32_t& r3, uint32_t addr) {
    asm volatile("ldmatrix.sync.aligned.m8n8.x4.shared.b16 {%0,%1,%2,%3}, [%4];"
                 : "=r"(r0), "=r"(r1), "=r"(r2), "=r"(r3) : "r"(addr));
}
__device__ __forceinline__ void ldm4t(uint32_t& r0, uint32_t& r1, uint32_t& r2,
                                      uint32_t& r3, uint32_t addr) {
    asm volatile("ldmatrix.sync.aligned.m8n8.x4.trans.shared.b16 {%0,%1,%2,%3}, [%4];"
                 : "=r"(r0), "=r"(r1), "=r"(r2), "=r"(r3) : "r"(addr));
}
__device__ __forceinline__ void mma_bf16(float* c, const uint32_t* a,
                                         uint32_t b0, uint32_t b1) {
    asm volatile(
        "mma.sync.aligned.m16n8k16.row.col.f32.bf16.bf16.f32 "
        "{%0,%1,%2,%3}, {%4,%5,%6,%7}, {%8,%9}, {%0,%1,%2,%3};"
        : "+f"(c[0]), "+f"(c[1]), "+f"(c[2]), "+f"(c[3])
        : "r"(a[0]), "r"(a[1]), "r"(a[2]), "r"(a[3]), "r"(b0), "r"(b1));
}
__device__ __forceinline__ void cp_async16(uint32_t smem_dst, const void* gsrc) {
    asm volatile("cp.async.cg.shared.global [%0], [%1], 16;"
                 :: "r"(smem_dst), "l"(gsrc) : "memory");
}
#define CP_COMMIT() asm volatile("cp.async.commit_group;" ::: "memory")
#define CP_WAIT0()  asm volatile("cp.async.wait_group 0;" ::: "memory")

// split fp32 float4 -> bf16 hi (8B) + bf16 lo (8B)
__device__ __forceinline__ void cvt_split(char* hi, char* lo, float4 v) {
    __nv_bfloat16 h0 = __float2bfloat16(v.x);
    __nv_bfloat16 h1 = __float2bfloat16(v.y);
    __nv_bfloat16 h2 = __float2bfloat16(v.z);
    __nv_bfloat16 h3 = __float2bfloat16(v.w);
    __nv_bfloat16 g0 = __float2bfloat16(v.x - __bfloat162float(h0));
    __nv_bfloat16 g1 = __float2bfloat16(v.y - __bfloat162float(h1));
    __nv_bfloat16 g2 = __float2bfloat16(v.z - __bfloat162float(h2));
    __nv_bfloat16 g3 = __float2bfloat16(v.w - __bfloat162float(h3));
    uint2 hp, lp;
    hp.x = (uint32_t)__bfloat16_as_ushort(h0) | ((uint32_t)__bfloat16_as_ushort(h1) << 16);
    hp.y = (uint32_t)__bfloat16_as_ushort(h2) | ((uint32_t)__bfloat16_as_ushort(h3) << 16);
    lp.x = (uint32_t)__bfloat16_as_ushort(g0) | ((uint32_t)__bfloat16_as_ushort(g1) << 16);
    lp.y = (uint32_t)__bfloat16_as_ushort(g2) | ((uint32_t)__bfloat16_as_ushort(g3) << 16);
    *(uint2*)hi = hp;
    *(uint2*)lo = lp;
}

// ============================================================================
// Kernel 1: logits GEMM — R4-exact structure. Pointers pre-offset per chunk;
// blockIdx.y in [0, CB).
// ============================================================================
static constexpr int L_AHI = 0;
static constexpr int L_ALO = 34816;             // 128*136*2
static constexpr int L_QHI = 69632;
static constexpr int L_QLO = 87040;             // + 64*136*2
static constexpr int L_TOTAL = 104448;

__global__ void __launch_bounds__(256, 2)
k_logits_mma(const float* __restrict__ qv, const float* __restrict__ A,
             float* __restrict__ logits) {
    extern __shared__ char sm[];
    const int tid = threadIdx.x;
    const int b = blockIdx.y, n0 = blockIdx.x * 128;

    const float* ab = A + ((size_t)b * Ns + n0) * Ds;
    #pragma unroll
    for (int g = 0; g < 2; g++) {
        float4 va[8];
        #pragma unroll
        for (int i = 0; i < 8; i++) {
            int f = tid + (g * 8 + i) * 256;
            va[i] = *(const float4*)(ab + (size_t)(f >> 5) * Ds + (f & 31) * 4);
        }
        #pragma unroll
        for (int i = 0; i < 8; i++) {
            int f = tid + (g * 8 + i) * 256;
            int off = ((f >> 5) * 136 + (f & 31) * 4) * 2;
            cvt_split(sm + L_AHI + off, sm + L_ALO + off, va[i]);
        }
    }
    const float* qb = qv + (size_t)b * Qs * Ds;
    {
        float4 vq[8];
        #pragma unroll
        for (int i = 0; i < 8; i++) {
            int f = tid + i * 256;
            vq[i] = *(const float4*)(qb + (size_t)(f >> 5) * Ds + (f & 31) * 4);
        }
        #pragma unroll
        for (int i = 0; i < 8; i++) {
            int f = tid + i * 256;
            int off = ((f >> 5) * 136 + (f & 31) * 4) * 2;
            cvt_split(sm + L_QHI + off, sm + L_QLO + off, vq[i]);
        }
    }
    __syncthreads();

    const int wid = tid >> 5, lane = tid & 31;
    const int wm = wid & 3;
    const int wq = wid >> 2;

    float acc[2][4][4];
    #pragma unroll
    for (int mi = 0; mi < 2; mi++)
        #pragma unroll
        for (int ni = 0; ni < 4; ni++)
            #pragma unroll
            for (int r = 0; r < 4; r++) acc[mi][ni][r] = 0.f;

    const uint32_t sb = smem_u32(sm);
    const int aoff[3] = { L_AHI, L_AHI, L_ALO };
    const int qoff[3] = { L_QHI, L_QLO, L_QHI };

    const uint32_t a_row = (uint32_t)(wm * 32 + (lane & 15));
    const uint32_t a_kb  = (uint32_t)(((lane >> 4) << 3) * 2);
    const uint32_t q_row0 = (uint32_t)(wq * 32 + ((lane >> 4) << 3) + (lane & 7));
    const uint32_t q_kb  = (uint32_t)((((lane >> 3) & 1) << 3) * 2);

    #pragma unroll
    for (int p = 0; p < 3; p++) {
        const uint32_t abase = sb + aoff[p] + a_row * 272 + a_kb;
        const uint32_t qbase = sb + qoff[p] + q_row0 * 272 + q_kb;
        #pragma unroll
        for (int k = 0; k < 8; k++) {
            uint32_t af[2][4];
            ldm4(af[0][0], af[0][1], af[0][2], af[0][3], abase + k * 32);
            ldm4(af[1][0], af[1][1], af[1][2], af[1][3], abase + 16 * 272 + k * 32);
            uint32_t bf[4][2];
            {
                uint32_t r0, r1, r2, r3;
                ldm4(r0, r1, r2, r3, qbase + k * 32);
                bf[0][0] = r0; bf[0][1] = r1; bf[1][0] = r2; bf[1][1] = r3;
                ldm4(r0, r1, r2, r3, qbase + 16 * 272 + k * 32);
                bf[2][0] = r0; bf[2][1] = r1; bf[3][0] = r2; bf[3][1] = r3;
            }
            #pragma unroll
            for (int mi = 0; mi < 2; mi++)
                #pragma unroll
                for (int ni = 0; ni < 4; ni++)
                    mma_bf16(acc[mi][ni], af[mi], bf[ni][0], bf[ni][1]);
        }
    }
    __syncthreads();

    float* sD = (float*)sm;
    const int group = lane >> 2, tc = lane & 3;
    #pragma unroll
    for (int mi = 0; mi < 2; mi++)
        #pragma unroll
        for (int ni = 0; ni < 4; ni++)
            #pragma unroll
            for (int r = 0; r < 4; r++) {
                int nl = wm * 32 + mi * 16 + group + ((r >> 1) << 3);
                int ql = wq * 32 + ni * 8 + (tc << 1) + (r & 1);
                sD[ql * 132 + nl] = acc[mi][ni][r];
            }
    __syncthreads();

    float* lb = logits + (size_t)b * Qs * Ns + n0;
    #pragma unroll
    for (int i = 0; i < 8; i++) {
        int f = tid + i * 256;
        int q = f >> 5, c4 = f & 31;
        float4 v = *(const float4*)&sD[q * 132 + c4 * 4];
        *(float4*)(lb + (size_t)q * Ns + c4 * 4) = v;
    }
}

// ============================================================================
// Kernel 2: masked max-free softmax over N per (b,q) row.
// ============================================================================
__global__ void k_softmax(const float* __restrict__ logits,
                          const int* __restrict__ node_nums,
                          float* __restrict__ prob) {
    const int bq  = blockIdx.x;
    const int b   = bq >> 6;
    const int nn  = node_nums[b];
    const int tid = threadIdx.x;

    const float* row = logits + (size_t)bq * Ns;
    float v[64];
    #pragma unroll
    for (int i = 0; i < 64; i++) v[i] = row[tid + i * 256];

    float s = 0.f;
    #pragma unroll
    for (int i = 0; i < 64; i++) {
        int n = tid + i * 256;
        float e = (n < nn) ? __expf(v[i]) : 0.f;
        v[i] = e;
        s += e;
    }
    __shared__ float reds[8];
    #pragma unroll
    for (int o = 16; o > 0; o >>= 1)
        s += __shfl_xor_sync(0xffffffffu, s, o);
    if ((tid & 31) == 0) reds[tid >> 5] = s;
    __syncthreads();
    {
        float t = 0.f;
        #pragma unroll
        for (int w = 0; w < 8; w++) t += reds[w];
        s = t;
    }

    const float inv = 1.f / s;
    float* prow = prob + (size_t)bq * Ns;
    #pragma unroll
    for (int i = 0; i < 64; i++) prow[tid + i * 256] = v[i] * inv;
}

// ============================================================================
// Kernel 3: res GEMM — cp.async staging pipeline (R13-exact).
// ============================================================================
static constexpr int R_PHI = 0;
static constexpr int R_PLO = 9216;              // 64*72*2
static constexpr int R_AHI = 18432;
static constexpr int R_ALO = 35840;             // + 64*136*2
static constexpr int R_SP  = 53248;             // fp32 P staging [64][64]
static constexpr int R_SA  = 69632;             // fp32 A staging [64][128]
static constexpr int R_TOTAL = 102400;

__global__ void __launch_bounds__(256, 2)
k_res_mma(const float* __restrict__ P, const float* __restrict__ A,
          float* __restrict__ res) {
    extern __shared__ char sm[];
    const int b = blockIdx.x;
    const int kbase = blockIdx.y * 512;
    const int tid = threadIdx.x;
    const int wid = tid >> 5, lane = tid & 31;
    const int wm = wid & 1;
    const int wd = wid >> 1;

    float acc[2][4][4];
    #pragma unroll
    for (int mi = 0; mi < 2; mi++)
        #pragma unroll
        for (int ni = 0; ni < 4; ni++)
            #pragma unroll
            for (int r = 0; r < 4; r++) acc[mi][ni][r] = 0.f;

    const float* pbase = P + (size_t)b * Qs * Ns;
    const float* abase = A + (size_t)b * Ns * Ds;
    const uint32_t sb = smem_u32(sm);

    const int poff[3] = { R_PHI, R_PHI, R_PLO };
    const int aoff[3] = { R_AHI, R_ALO, R_AHI };

    const uint32_t p_row = (uint32_t)(wm * 32 + (lane & 15));
    const uint32_t p_kb  = (uint32_t)(((lane >> 4) << 3) * 2);
    const uint32_t a_krow0 = (uint32_t)((((lane >> 3) & 1) << 3) + (lane & 7));
    const uint32_t a_dcol  = (uint32_t)((wd * 32 + ((lane >> 4) << 3)) * 2);

    {
        const int kk = kbase;
        #pragma unroll
        for (int i = 0; i < 4; i++) {
            int f = tid + i * 256;
            cp_async16(sb + R_SP + f * 16,
                       pbase + (size_t)(f >> 4) * Ns + kk + (f & 15) * 4);
        }
        #pragma unroll
        for (int i = 0; i < 8; i++) {
            int f = tid + i * 256;
            cp_async16(sb + R_SA + f * 16,
                       abase + (size_t)(kk + (f >> 5)) * Ds + (f & 31) * 4);
        }
        CP_COMMIT();
    }

    for (int kt = 0; kt < 8; kt++) {
        CP_WAIT0();
        __syncthreads();

        #pragma unroll
        for (int i = 0; i < 4; i++) {
            int f = tid + i * 256;
            float4 v = *(const float4*)(sm + R_SP + f * 16);
            int off = ((f >> 4) * 72 + (f & 15) * 4) * 2;
            cvt_split(sm + R_PHI + off, sm + R_PLO + off, v);
        }
        #pragma unroll
        for (int i = 0; i < 8; i++) {
            int f = tid + i * 256;
            float4 v = *(const float4*)(sm + R_SA + f * 16);
            int off = ((f >> 5) * 136 + (f & 31) * 4) * 2;
            cvt_split(sm + R_AHI + off, sm + R_ALO + off, v);
        }
        __syncthreads();

        if (kt < 7) {
            const int kk2 = kbase + (kt + 1) * 64;
            #pragma unroll
            for (int i = 0; i < 4; i++) {
                int f = tid + i * 256;
                cp_async16(sb + R_SP + f * 16,
                           pbase + (size_t)(f >> 4) * Ns + kk2 + (f & 15) * 4);
            }
            #pragma unroll
            for (int i = 0; i < 8; i++) {
                int f = tid + i * 256;
                cp_async16(sb + R_SA + f * 16,
                           abase + (size_t)(kk2 + (f >> 5)) * Ds + (f & 31) * 4);
            }
            CP_COMMIT();
        }

        #pragma unroll
        for (int p = 0; p < 3; p++) {
            const uint32_t pb_ = sb + poff[p] + p_row * 144 + p_kb;
            const uint32_t ab_ = sb + aoff[p] + a_krow0 * 272 + a_dcol;
            #pragma unroll
            for (int k = 0; k < 4; k++) {
                uint32_t af[2][4];
                ldm4(af[0][0], af[0][1], af[0][2], af[0][3], pb_ + k * 32);
                ldm4(af[1][0], af[1][1], af[1][2], af[1][3], pb_ + 16 * 144 + k * 32);
                uint32_t bfr[4][2];
                {
                    uint32_t r0, r1, r2, r3;
                    ldm4t(r0, r1, r2, r3, ab_ + k * 16 * 272);
                    bfr[0][0] = r0; bfr[0][1] = r1; bfr[1][0] = r2; bfr[1][1] = r3;
                    ldm4t(r0, r1, r2, r3, ab_ + k * 16 * 272 + 16 * 2);
                    bfr[2][0] = r0; bfr[2][1] = r1; bfr[3][0] = r2; bfr[3][1] = r3;
                }
                #pragma unroll
                for (int mi = 0; mi < 2; mi++)
                    #pragma unroll
                    for (int ni = 0; ni < 4; ni++)
                        mma_bf16(acc[mi][ni], af[mi], bfr[ni][0], bfr[ni][1]);
            }
        }
    }

    const int group = lane >> 2, tc = lane & 3;
    float* rb = res + (size_t)b * Qs * Ds;
    #pragma unroll
    for (int mi = 0; mi < 2; mi++)
        #pragma unroll
        for (int ni = 0; ni < 4; ni++)
            #pragma unroll
            for (int r = 0; r < 4; r++) {
                int q = wm * 32 + mi * 16 + group + ((r >> 1) << 3);
                int d = wd * 32 + ni * 8 + (tc << 1) + (r & 1);
                atomicAdd(rb + (size_t)q * Ds + d, acc[mi][ni][r]);
            }
}

// ---------------------------------------------------------------------------
// 4-way batch-chunked stream pipeline. Streams/events created lazily on the
// host (no device memory). Fork/join via events keeps it graph-capturable.
// ---------------------------------------------------------------------------
extern "C" void kernel_launch(void* const* d_in, const int* in_sizes, int n_in,
                              void* d_out, int out_size) {
    const float* qv = (const float*)d_in[0];
    const float* A  = (const float*)d_in[1];
    const int*   nn = (const int*)d_in[2];

    float* out_res  = (float*)d_out;                        // [B,Q,D]
    float* out_soft = out_res  + (size_t)Bsz * Qs * Ds;     // [B,Q,N]
    float* out_log  = out_soft + (size_t)Bsz * Qs * Ns;     // [B,Q,N]

    static cudaStream_t strm[NCHUNK] = {};
    static cudaEvent_t  ev_fork = nullptr;
    static cudaEvent_t  ev_join[NCHUNK] = {};
    static bool init_done = false;
    if (!init_done) {
        for (int c = 1; c < NCHUNK; c++)
            cudaStreamCreateWithFlags(&strm[c], cudaStreamNonBlocking);
        cudaEventCreateWithFlags(&ev_fork, cudaEventDisableTiming);
        for (int c = 1; c < NCHUNK; c++)
            cudaEventCreateWithFlags(&ev_join[c], cudaEventDisableTiming);
        cudaFuncSetAttribute(k_logits_mma,
                             cudaFuncAttributeMaxDynamicSharedMemorySize, L_TOTAL);
        cudaFuncSetAttribute(k_res_mma,
                             cudaFuncAttributeMaxDynamicSharedMemorySize, R_TOTAL);
        init_done = true;
    }

    cudaMemsetAsync(out_res, 0, (size_t)Bsz * Qs * Ds * sizeof(float), 0);
    cudaEventRecord(ev_fork, 0);

    for (int c = 0; c < NCHUNK; c++) {
        cudaStream_t s = (c == 0) ? (cudaStream_t)0 : strm[c];
        if (c > 0) cudaStreamWaitEvent(s, ev_fork, 0);

        const size_t obq = (size_t)c * CB * Qs;            // (b,q) row offset
        const float* qv_c  = qv      + obq * Ds;
        const float* A_c   = A       + (size_t)c * CB * Ns * Ds;
        const int*   nn_c  = nn      + c * CB;
        float* log_c  = out_log  + obq * Ns;
        float* soft_c = out_soft + obq * Ns;
        float* res_c  = out_res  + obq * Ds;

        k_logits_mma<<<dim3(Ns / 128, CB), 256, L_TOTAL, s>>>(qv_c, A_c, log_c);
        k_softmax<<<CB * Qs, 256, 0, s>>>(log_c, nn_c, soft_c);
        k_res_mma<<<dim3(CB, 32), 256, R_TOTAL, s>>>(soft_c, A_c, res_c);

        if (c > 0) {
            cudaEventRecord(ev_join[c], s);
            cudaStreamWaitEvent(0, ev_join[c], 0);
        }
    }
}